// round 1
// baseline (speedup 1.0000x reference)
#include <cuda_runtime.h>
#include <math.h>

// ---------------------------------------------------------------------------
// Problem dims
// ---------------------------------------------------------------------------
#define T_STEPS 16
#define B_SZ    32
#define C_IN    2048
#define MEM_SZ  512
#define N_CLS   8
#define C_CAM   1000
#define HW      49          // 7x7
#define PADHW   81          // 9x9 padded
#define KX      (C_IN*9)    // 18432  (x part of K)
#define KH      (MEM_SZ*9)  // 4608   (h part of K)
#define NSTRIDE ((C_IN+MEM_SZ)*9) // 23040, row stride of main weights
#define MBIG    (T_STEPS*B_SZ*HW) // 25088
#define MSTEP   (B_SZ*HW)         // 1568
#define TB      (T_STEPS*B_SZ)    // 512

// ---------------------------------------------------------------------------
// Static device scratch (allocation-free rule: __device__ globals)
// ---------------------------------------------------------------------------
__device__ float g_xpad[TB * C_IN * PADHW];       // padded (then attention-scaled) input, ~340MB
__device__ float g_preS0[MBIG];                   // attention gate pre-acts (x part): fi
__device__ float g_preS1[MBIG];                   // c
__device__ float g_preS2[MBIG];                   // o
__device__ float g_attmap[MBIG];                  // CAM softmax map
__device__ float g_s[MBIG];                       // softmax(a) per step
__device__ float g_a[B_SZ * HW];                  // attention state a
__device__ float g_cs[B_SZ * HW];                 // attention cell state
__device__ float g_pooled[TB * C_IN];
__device__ float g_logits[TB * C_CAM];
__device__ int   g_idx[TB];
__device__ float g_cam[TB * HW];
__device__ float g_preM0[MBIG * MEM_SZ];          // main gate pre-acts (x_att part), 51MB each
__device__ float g_preM1[MBIG * MEM_SZ];
__device__ float g_preM2[MBIG * MEM_SZ];
__device__ float g_hpad[B_SZ * MEM_SZ * PADHW];   // padded h state
__device__ float g_cstate[MSTEP * MEM_SZ];        // main cell state [m][n]
__device__ float g_hpre0[MSTEP * MEM_SZ];         // per-step h-part GEMM out
__device__ float g_hpre1[MSTEP * MEM_SZ];
__device__ float g_hpre2[MSTEP * MEM_SZ];

__device__ __forceinline__ float sigmoidf_(float x) { return 1.0f / (1.0f + expf(-x)); }

// ---------------------------------------------------------------------------
// Zero recurrent states (every call -> deterministic)
// ---------------------------------------------------------------------------
__global__ void zero_states() {
    int i = blockIdx.x * 256 + threadIdx.x;
    if (i < B_SZ * MEM_SZ * PADHW) g_hpad[i] = 0.f;
    if (i < MSTEP * MEM_SZ)        g_cstate[i] = 0.f;
    if (i < B_SZ * HW)             { g_a[i] = 0.f; g_cs[i] = 0.f; }
}

// ---------------------------------------------------------------------------
// Build zero-padded input: xpad[(tb*C + c)*81 + ph*9+pw]
// ---------------------------------------------------------------------------
__global__ void pad_x(const float* __restrict__ x) {
    int lin = blockIdx.x * 256 + threadIdx.x;
    const int TOT = TB * C_IN * PADHW;
    if (lin >= TOT) return;
    int p  = lin % PADHW;
    int rc = lin / PADHW;            // tb*C_IN + c
    int ph = p / 9, pw = p % 9;
    float v = 0.f;
    if (ph >= 1 && ph <= 7 && pw >= 1 && pw <= 7)
        v = x[rc * HW + (ph - 1) * 7 + (pw - 1)];
    g_xpad[lin] = v;
}

// ---------------------------------------------------------------------------
// Attention-gate x contributions: preS[g][m] = sum_k xrow[k] * Ws_g[k], K=18432
// one block per m=(t,b,hw)
// ---------------------------------------------------------------------------
__global__ void preS_kernel(const float* __restrict__ Wfi,
                            const float* __restrict__ Wc,
                            const float* __restrict__ Wo) {
    int m   = blockIdx.x;
    int tb  = m / HW, hw = m % HW;
    int h   = hw / 7, w = hw % 7;
    int tid = threadIdx.x;
    const float* ap = &g_xpad[(size_t)tb * C_IN * PADHW];
    float a0 = 0.f, a1 = 0.f, a2 = 0.f;
    for (int k = tid; k < KX; k += 256) {
        int c = k / 9, r = k % 9;
        int kh = r / 3, kw = r % 3;
        float v = ap[c * PADHW + (h + kh) * 9 + (w + kw)];
        a0 += v * Wfi[k];
        a1 += v * Wc[k];
        a2 += v * Wo[k];
    }
    __shared__ float red[256];
    red[tid] = a0; __syncthreads();
    for (int s = 128; s > 0; s >>= 1) { if (tid < s) red[tid] += red[tid + s]; __syncthreads(); }
    if (tid == 0) g_preS0[m] = red[0];
    __syncthreads();
    red[tid] = a1; __syncthreads();
    for (int s = 128; s > 0; s >>= 1) { if (tid < s) red[tid] += red[tid + s]; __syncthreads(); }
    if (tid == 0) g_preS1[m] = red[0];
    __syncthreads();
    red[tid] = a2; __syncthreads();
    for (int s = 128; s > 0; s >>= 1) { if (tid < s) red[tid] += red[tid + s]; __syncthreads(); }
    if (tid == 0) g_preS2[m] = red[0];
}

// ---------------------------------------------------------------------------
// CAM pipeline
// ---------------------------------------------------------------------------
__global__ void pooled_kernel(const float* __restrict__ x) {
    int lin = blockIdx.x * 256 + threadIdx.x;   // tb*C_IN + c
    if (lin >= TB * C_IN) return;
    const float* p = x + (size_t)lin * HW;
    float s = 0.f;
    #pragma unroll
    for (int i = 0; i < HW; i++) s += p[i];
    g_pooled[lin] = s * (1.0f / 49.0f);
}

__global__ void cam_logits_kernel(const float* __restrict__ W_cam) {
    int gw   = blockIdx.x * 4 + (threadIdx.x >> 5);
    int lane = threadIdx.x & 31;
    if (gw >= TB * C_CAM) return;
    int tb = gw / C_CAM, j = gw % C_CAM;
    const float* p  = &g_pooled[tb * C_IN];
    const float* wr = &W_cam[(size_t)j * C_IN];
    float acc = 0.f;
    for (int c = lane; c < C_IN; c += 32) acc += p[c] * wr[c];
    #pragma unroll
    for (int o = 16; o > 0; o >>= 1) acc += __shfl_down_sync(0xffffffffu, acc, o);
    if (lane == 0) g_logits[gw] = acc;
}

__global__ void argmax_kernel() {
    int tb = blockIdx.x, tid = threadIdx.x;
    float best = -INFINITY; int bi = 0;
    for (int j = tid; j < C_CAM; j += 256) {
        float v = g_logits[tb * C_CAM + j];
        if (v > best) { best = v; bi = j; }
    }
    __shared__ float sv[256]; __shared__ int si[256];
    sv[tid] = best; si[tid] = bi; __syncthreads();
    for (int s = 128; s > 0; s >>= 1) {
        if (tid < s) {
            float v2 = sv[tid + s]; int i2 = si[tid + s];
            if (v2 > sv[tid] || (v2 == sv[tid] && i2 < si[tid])) { sv[tid] = v2; si[tid] = i2; }
        }
        __syncthreads();
    }
    if (tid == 0) g_idx[tb] = si[0];
}

__global__ void cam_kernel(const float* __restrict__ x, const float* __restrict__ W_cam) {
    int gw   = blockIdx.x * 8 + (threadIdx.x >> 5);
    int lane = threadIdx.x & 31;
    if (gw >= TB * HW) return;
    int tb = gw / HW, hw = gw % HW;
    const float* wsel = &W_cam[(size_t)g_idx[tb] * C_IN];
    const float* xp   = x + (size_t)tb * C_IN * HW + hw;
    float acc = 0.f;
    for (int c = lane; c < C_IN; c += 32) acc += wsel[c] * xp[(size_t)c * HW];
    #pragma unroll
    for (int o = 16; o > 0; o >>= 1) acc += __shfl_down_sync(0xffffffffu, acc, o);
    if (lane == 0) g_cam[gw] = acc;
}

__global__ void cam_softmax_kernel() {
    int tb = blockIdx.x, tid = threadIdx.x; // 64 threads
    __shared__ float v[HW]; __shared__ float red[64];
    if (tid < HW) v[tid] = g_cam[tb * HW + tid];
    __syncthreads();
    float m = (tid < HW) ? v[tid] : -INFINITY;
    red[tid] = m; __syncthreads();
    for (int s = 32; s > 0; s >>= 1) { if (tid < s) red[tid] = fmaxf(red[tid], red[tid + s]); __syncthreads(); }
    float mx = red[0]; __syncthreads();
    float e = (tid < HW) ? expf(v[tid] - mx) : 0.f;
    red[tid] = e; __syncthreads();
    for (int s = 32; s > 0; s >>= 1) { if (tid < s) red[tid] += red[tid + s]; __syncthreads(); }
    if (tid < HW) g_attmap[tb * HW + tid] = e / red[0];
}

// ---------------------------------------------------------------------------
// Attention recurrence, one step (32 blocks x 64 threads)
// ---------------------------------------------------------------------------
__global__ void att_step(int t,
                         const float* __restrict__ Wfi, const float* __restrict__ Wc,
                         const float* __restrict__ Wo,
                         const float* __restrict__ bfi, const float* __restrict__ bc,
                         const float* __restrict__ bo) {
    int b = blockIdx.x, tid = threadIdx.x;
    __shared__ float ap[HW]; __shared__ float av[HW]; __shared__ float red[64];
    if (tid < HW) ap[tid] = g_a[b * HW + tid];
    __syncthreads();
    if (tid < HW) {
        int h = tid / 7, w = tid % 7;
        float efi = 0.f, ec = 0.f, eo = 0.f;
        #pragma unroll
        for (int kh = 0; kh < 3; kh++)
            #pragma unroll
            for (int kw = 0; kw < 3; kw++) {
                int hh = h + kh - 1, ww = w + kw - 1;
                if (hh >= 0 && hh < 7 && ww >= 0 && ww < 7) {
                    float aval = ap[hh * 7 + ww];
                    int off = KX + kh * 3 + kw;
                    efi += aval * Wfi[off];
                    ec  += aval * Wc[off];
                    eo  += aval * Wo[off];
                }
            }
        int base = (t * B_SZ + b) * HW + tid;
        float fi = sigmoidf_(g_preS0[base] + efi + bfi[0]);
        float o  = sigmoidf_(g_preS2[base] + eo + bo[0]);
        float cc = tanhf(g_preS1[base] + ec + bc[0]);
        float cs = fi * g_cs[b * HW + tid] + (1.0f - fi) * cc;
        g_cs[b * HW + tid] = cs;
        float an = o * tanhf(cs) * g_attmap[base];
        g_a[b * HW + tid] = an;
        av[tid] = an;
    }
    __syncthreads();
    float m = (tid < HW) ? av[tid] : -INFINITY;
    red[tid] = m; __syncthreads();
    for (int s = 32; s > 0; s >>= 1) { if (tid < s) red[tid] = fmaxf(red[tid], red[tid + s]); __syncthreads(); }
    float mx = red[0]; __syncthreads();
    float e = (tid < HW) ? expf(av[tid] - mx) : 0.f;
    red[tid] = e; __syncthreads();
    for (int s = 32; s > 0; s >>= 1) { if (tid < s) red[tid] += red[tid + s]; __syncthreads(); }
    if (tid < HW) g_s[(t * B_SZ + b) * HW + tid] = e / red[0];
}

// ---------------------------------------------------------------------------
// x_att = x * softmax(a): scale padded input in place (borders remain 0)
// ---------------------------------------------------------------------------
__global__ void scale_x() {
    int lin = blockIdx.x * 256 + threadIdx.x;
    const int TOT = TB * C_IN * HW;
    if (lin >= TOT) return;
    int hw = lin % HW;
    int rc = lin / HW;             // tb*C_IN + c
    int tb = rc / C_IN;
    float sc = g_s[tb * HW + hw];
    int p = (hw / 7 + 1) * 9 + (hw % 7 + 1);
    g_xpad[(size_t)rc * PADHW + p] *= sc;
}

// ---------------------------------------------------------------------------
// Implicit-GEMM conv: O_g[m*512+n] = sum_k A[m,k] * W_g[n*nstride + kbase + k]
// A gathered from padded buffer: rows (tb*C + c), k = (c, kh, kw)
// Tiles: 128x64x16, 256 threads, 8x4 per thread.
// ---------------------------------------------------------------------------
#define GBM 128
#define GBN 64
#define GBK 16

__global__ __launch_bounds__(256) void conv_gemm(
    const float* __restrict__ Apad, int C, int M, int K,
    const float* __restrict__ W0, const float* __restrict__ W1, const float* __restrict__ W2,
    int nstride, int kbase,
    float* __restrict__ O0, float* __restrict__ O1, float* __restrict__ O2) {

    const float* Wg = (blockIdx.z == 0) ? W0 : (blockIdx.z == 1 ? W1 : W2);
    float*       Og = (blockIdx.z == 0) ? O0 : (blockIdx.z == 1 ? O1 : O2);

    __shared__ float As[GBK][GBM];
    __shared__ float Bs[GBK][GBN + 4];

    int m0  = blockIdx.x * GBM;
    int n0  = blockIdx.y * GBN;
    int tid = threadIdx.x;
    int tx  = tid & 15;        // n dir
    int ty  = tid >> 4;        // m dir

    // A-load geometry: fixed per thread
    int ml = tid & 127;
    int khalf = tid >> 7;      // 0/1
    int m = m0 + ml;
    bool mvalid = (m < M);
    int abase = 0;
    int hh = 0, ww = 0;
    if (mvalid) {
        int tb = m / HW, hw = m % HW;
        hh = hw / 7; ww = hw % 7;
        abase = tb * C * PADHW;
    }
    // B-load geometry: fixed per thread
    int bk = tid & 15;
    int bn = tid >> 4;          // 0..15, + 16*i

    float acc[8][4];
    #pragma unroll
    for (int i = 0; i < 8; i++)
        #pragma unroll
        for (int j = 0; j < 4; j++) acc[i][j] = 0.f;

    for (int k0 = 0; k0 < K; k0 += GBK) {
        // ---- load A tile (8 elems/thread, kk = khalf + 2i) ----
        #pragma unroll
        for (int i = 0; i < 8; i++) {
            int kk = khalf + 2 * i;
            float v = 0.f;
            if (mvalid) {
                int k = k0 + kk;
                int c = k / 9, r = k % 9;
                v = Apad[abase + c * PADHW + (hh + r / 3) * 9 + (ww + r % 3)];
            }
            As[kk][ml] = v;
        }
        // ---- load B tile (4 elems/thread) ----
        #pragma unroll
        for (int i = 0; i < 4; i++) {
            int nl = bn + 16 * i;
            Bs[bk][nl] = Wg[(size_t)(n0 + nl) * nstride + kbase + k0 + bk];
        }
        __syncthreads();
        // ---- compute ----
        #pragma unroll
        for (int kk = 0; kk < GBK; kk++) {
            float4 a0 = *(const float4*)&As[kk][ty * 8];
            float4 a1 = *(const float4*)&As[kk][ty * 8 + 4];
            float4 bb = *(const float4*)&Bs[kk][tx * 4];
            float ar[8] = {a0.x, a0.y, a0.z, a0.w, a1.x, a1.y, a1.z, a1.w};
            float br[4] = {bb.x, bb.y, bb.z, bb.w};
            #pragma unroll
            for (int i = 0; i < 8; i++)
                #pragma unroll
                for (int j = 0; j < 4; j++) acc[i][j] += ar[i] * br[j];
        }
        __syncthreads();
    }
    // ---- store ----
    #pragma unroll
    for (int i = 0; i < 8; i++) {
        int mm = m0 + ty * 8 + i;
        if (mm < M) {
            float4 v = make_float4(acc[i][0], acc[i][1], acc[i][2], acc[i][3]);
            *(float4*)&Og[(size_t)mm * MEM_SZ + n0 + tx * 4] = v;
        }
    }
}

// ---------------------------------------------------------------------------
// Main gate update, one step
// ---------------------------------------------------------------------------
__global__ void gate_step(int t, const float* __restrict__ bfi,
                          const float* __restrict__ bc, const float* __restrict__ bo) {
    int lin = blockIdx.x * 256 + threadIdx.x;
    if (lin >= MSTEP * MEM_SZ) return;
    int n = lin & (MEM_SZ - 1);
    int m = lin >> 9;            // MEM_SZ = 512
    int b = m / HW, hw = m % HW;
    size_t bigOff = ((size_t)t * MSTEP + m) * MEM_SZ + n;
    float pfi = g_preM0[bigOff] + g_hpre0[lin] + bfi[n];
    float pc  = g_preM1[bigOff] + g_hpre1[lin] + bc[n];
    float po  = g_preM2[bigOff] + g_hpre2[lin] + bo[n];
    float fi = sigmoidf_(pfi);
    float o  = sigmoidf_(po);
    float cn = fi * g_cstate[lin] + (1.0f - fi) * tanhf(pc);
    g_cstate[lin] = cn;
    float h = o * tanhf(cn);
    g_hpad[(size_t)(b * MEM_SZ + n) * PADHW + (hw / 7 + 1) * 9 + (hw % 7 + 1)] = h;
}

// ---------------------------------------------------------------------------
// Final: feats = mean_hw(h); logits = feats @ W_fc^T + b_fc
// ---------------------------------------------------------------------------
__global__ void final_kernel(const float* __restrict__ W_fc, const float* __restrict__ b_fc,
                             float* __restrict__ logitsOut, float* __restrict__ featsOut) {
    int b = blockIdx.x, n = threadIdx.x; // 512 threads
    const float* hp = &g_hpad[(size_t)(b * MEM_SZ + n) * PADHW];
    float s = 0.f;
    #pragma unroll
    for (int hh = 1; hh <= 7; hh++)
        #pragma unroll
        for (int ww = 1; ww <= 7; ww++) s += hp[hh * 9 + ww];
    float f = s * (1.0f / 49.0f);
    __shared__ float fs[MEM_SZ];
    fs[n] = f;
    if (featsOut) featsOut[b * MEM_SZ + n] = f;
    __syncthreads();
    if (n < N_CLS && logitsOut) {
        float acc = b_fc[n];
        for (int k = 0; k < MEM_SZ; k++) acc += fs[k] * W_fc[n * MEM_SZ + k];
        logitsOut[b * N_CLS + n] = acc;
    }
}

// ---------------------------------------------------------------------------
// Host launcher
// ---------------------------------------------------------------------------
extern "C" void kernel_launch(void* const* d_in, const int* in_sizes, int n_in,
                              void* d_out, int out_size) {
    const float* x     = (const float*)d_in[0];
    const float* W_fi  = (const float*)d_in[1];
    const float* b_fi  = (const float*)d_in[2];
    const float* W_c   = (const float*)d_in[3];
    const float* b_c   = (const float*)d_in[4];
    const float* W_o   = (const float*)d_in[5];
    const float* b_o   = (const float*)d_in[6];
    const float* Ws_fi = (const float*)d_in[7];
    const float* bs_fi = (const float*)d_in[8];
    const float* Ws_c  = (const float*)d_in[9];
    const float* bs_c  = (const float*)d_in[10];
    const float* Ws_o  = (const float*)d_in[11];
    const float* bs_o  = (const float*)d_in[12];
    const float* W_cam = (const float*)d_in[13];
    const float* W_fc  = (const float*)d_in[14];
    const float* b_fc  = (const float*)d_in[15];

    float* xpad; cudaGetSymbolAddress((void**)&xpad, g_xpad);
    float* hpad; cudaGetSymbolAddress((void**)&hpad, g_hpad);
    float* pm0;  cudaGetSymbolAddress((void**)&pm0, g_preM0);
    float* pm1;  cudaGetSymbolAddress((void**)&pm1, g_preM1);
    float* pm2;  cudaGetSymbolAddress((void**)&pm2, g_preM2);
    float* hp0;  cudaGetSymbolAddress((void**)&hp0, g_hpre0);
    float* hp1;  cudaGetSymbolAddress((void**)&hp1, g_hpre1);
    float* hp2;  cudaGetSymbolAddress((void**)&hp2, g_hpre2);

    float* outF = (float*)d_out;
    float* lp = nullptr; float* fp = nullptr;
    if (out_size >= B_SZ * N_CLS + B_SZ * MEM_SZ) { lp = outF; fp = outF + B_SZ * N_CLS; }
    else if (out_size == B_SZ * MEM_SZ)           { fp = outF; }
    else                                          { lp = outF; }

    // 1. reset recurrent state
    zero_states<<<(B_SZ * MEM_SZ * PADHW + 255) / 256, 256>>>();
    // 2. pad input
    pad_x<<<(TB * C_IN * PADHW + 255) / 256, 256>>>(x);
    // 3. attention-gate x contributions (all t)
    preS_kernel<<<MBIG, 256>>>(Ws_fi, Ws_c, Ws_o);
    // 4. CAM pipeline (all t)
    pooled_kernel<<<(TB * C_IN + 255) / 256, 256>>>(x);
    cam_logits_kernel<<<(TB * C_CAM + 3) / 4, 128>>>(W_cam);
    argmax_kernel<<<TB, 256>>>();
    cam_kernel<<<(TB * HW + 7) / 8, 256>>>(x, W_cam);
    cam_softmax_kernel<<<TB, 64>>>();
    // 5. sequential attention recurrence (cheap)
    for (int t = 0; t < T_STEPS; t++)
        att_step<<<B_SZ, 64>>>(t, Ws_fi, Ws_c, Ws_o, bs_fi, bs_c, bs_o);
    // 6. apply attention scaling in place
    scale_x<<<(TB * C_IN * HW + 255) / 256, 256>>>();
    // 7. giant parallel GEMM: x_att conv contributions for all t, 3 gates
    {
        dim3 grid((MBIG + GBM - 1) / GBM, MEM_SZ / GBN, 3);
        conv_gemm<<<grid, 256>>>(xpad, C_IN, MBIG, KX,
                                 W_fi, W_c, W_o, NSTRIDE, 0, pm0, pm1, pm2);
    }
    // 8. sequential main recurrence: h-part GEMM + gates per step
    for (int t = 0; t < T_STEPS; t++) {
        dim3 grid((MSTEP + GBM - 1) / GBM, MEM_SZ / GBN, 3);
        conv_gemm<<<grid, 256>>>(hpad, MEM_SZ, MSTEP, KH,
                                 W_fi, W_c, W_o, NSTRIDE, KX, hp0, hp1, hp2);
        gate_step<<<(MSTEP * MEM_SZ + 255) / 256, 256>>>(t, b_fi, b_c, b_o);
    }
    // 9. final pooling + FC head
    final_kernel<<<B_SZ, MEM_SZ>>>(W_fc, b_fc, lp, fp);
}